// round 10
// baseline (speedup 1.0000x reference)
#include <cuda_runtime.h>
#include <cuda_fp16.h>
#include <cstdint>

// ---------------------------------------------------------------------------
// Conversation_Self_Attention: B=64, S=512, D=DK=DV=512  (sm_103 mma.sync;
// tcgen05 unavailable in this bench path)
//
// fp16 HMMA (m16n8k16, fp32 accum), ldmatrix, 128x256 CTA tile, 256 thr /
// 8 warps (2x4 grid of 64x64 warp tiles), BK=64, 3-stage cp.async,
// ONE barrier per k-chunk, register fragment double-buffering.
// cp.async ops/FLOP cut 25% vs 128x128 (LSU-issue was the binding constraint).
//
//   Qc = [ half((sent@Wq^T+bq)*2^-5) | half((pos@Wpq^T+bpq)*2^-5) ] [B*S,1024]
//   Kc = [ half(sent@Wk^T+bk)        | half(pos@Wpk^T+bpk)        ] [B*S,1024]
//   V  =   half(sent@Wv^T+bv)                                       [B*S,512]
//   scores[b] = Qc_b @ Kc_b^T + bias   (fp32)
//   att = softmax(scores) -> d_out[0:B*S*S] fp32 + half copy
//   out[b] = att_b @ V_b^T -> d_out[B*S*S:] fp32
// ---------------------------------------------------------------------------

#define BM 128
#define BN 256
#define BK 64                 // halves per k-chunk (128B)
#define BKP 72                // padded row (144B): conflict-free ldmatrix
#define NSTAGE 3
#define THREADS 256
#define TILE_A (BM * BKP)                      // 9216 halves
#define TILE_B (BN * BKP)                      // 18432 halves
#define STAGE_H (TILE_A + TILE_B)              // 27648 halves
#define SMEM_BYTES (NSTAGE * STAGE_H * 2)      // 165888

static const int Bv = 64, Sv = 512;

// scratch (static device arrays: allocation-free contract)
__device__ __align__(128) __half g_Ah[64L * 512 * 512];
__device__ __align__(128) __half g_Ph[64L * 512 * 512];
__device__ __align__(128) __half g_Wh[5L * 512 * 512];
__device__ __align__(128) __half g_Qc[64L * 512 * 1024];
__device__ __align__(128) __half g_Kc[64L * 512 * 1024];
__device__ __align__(128) __half g_V [64L * 512 * 512];
__device__ __align__(128) __half g_At[64L * 512 * 512];
__device__ float g_S[64L * 512 * 512];

__device__ __forceinline__ uint32_t smem_u32(const void* p) {
    uint32_t a;
    asm("{ .reg .u64 t; cvta.to.shared.u64 t, %1; cvt.u32.u64 %0, t; }" : "=r"(a) : "l"(p));
    return a;
}

#define LDSM_X4(r0, r1, r2, r3, addr)                                  \
    asm volatile("ldmatrix.sync.aligned.m8n8.x4.shared.b16 "           \
                 "{%0, %1, %2, %3}, [%4];"                             \
                 : "=r"(r0), "=r"(r1), "=r"(r2), "=r"(r3) : "r"(addr))

// ---------------- fp16 NT GEMM: C[z] = (A[z] @ B[z]^T + bias) * alpha -------
template <typename OutT>
__global__ void __launch_bounds__(THREADS, 1)
gemm_nt_f16(const __half* __restrict__ A, int lda, long As,
            const __half* __restrict__ B, int ldb, long Bs,
            const float* __restrict__ bias, float alpha,
            OutT* __restrict__ C, int ldc, long Cs,
            int K)
{
    extern __shared__ __half smem[];

    const int tid  = threadIdx.x;
    const int lane = tid & 31;
    const int warp = tid >> 5;
    const int wm   = warp & 1;            // 2 warps in M -> 64 rows/warp
    const int wn   = warp >> 1;           // 4 warps in N -> 64 cols/warp

    const int bm = blockIdx.x * BM;
    const int bn = blockIdx.y * BN;
    const int z  = blockIdx.z;

    const __half* Ab = A + (size_t)z * As;
    const __half* Bb = B + (size_t)z * Bs;
    OutT*         Cb = C + (size_t)z * Cs;

    // cp.async coords: 128B global rows = 8 x 16B chunks (256 thr -> 32 rows/pass)
    const int row8 = tid >> 3;            // 0..31
    const int ch   = tid & 7;

    // ldmatrix per-thread coords (mapping verified R5-R9)
    const int g  = lane >> 3;             // matrix index 0..3
    const int lr = lane & 7;
    const uint32_t a_base = (uint32_t)(((wm * 64 + (g & 1) * 8 + lr) * BKP) + (g >> 1) * 8) * 2;
    const uint32_t b_base = (uint32_t)(((wn * 64 + (g >> 1) * 8 + lr) * BKP) + (g & 1) * 8) * 2
                          + TILE_A * 2;

    const uint32_t smem0 = smem_u32(smem);

    float acc[4][8][4];
    #pragma unroll
    for (int i = 0; i < 4; i++)
        #pragma unroll
        for (int j = 0; j < 8; j++)
            #pragma unroll
            for (int k = 0; k < 4; k++) acc[i][j][k] = 0.f;

    unsigned afr[2][4][4], bfr[2][8][2];

    auto load_tile = [&](int kt) {
        const int st = kt % NSTAGE;
        __half* dA = smem + st * STAGE_H;
        __half* dB = dA + TILE_A;
        const int k0 = kt * BK;
        // A: 128 rows / 32 = 4 passes
        #pragma unroll
        for (int i = 0; i < 4; i++) {
            const int row = row8 + i * 32;
            const __half* gp = Ab + (size_t)(bm + row) * lda + k0 + ch * 8;
            unsigned s = (unsigned)__cvta_generic_to_shared(dA + row * BKP + ch * 8);
            asm volatile("cp.async.cg.shared.global [%0], [%1], 16;\n" :: "r"(s), "l"(gp));
        }
        // B: 256 rows / 32 = 8 passes
        #pragma unroll
        for (int i = 0; i < 8; i++) {
            const int row = row8 + i * 32;
            const __half* gp = Bb + (size_t)(bn + row) * ldb + k0 + ch * 8;
            unsigned s = (unsigned)__cvta_generic_to_shared(dB + row * BKP + ch * 8);
            asm volatile("cp.async.cg.shared.global [%0], [%1], 16;\n" :: "r"(s), "l"(gp));
        }
        asm volatile("cp.async.commit_group;\n");
    };

    auto frag_load = [&](int buf, uint32_t stageAddr, int kb) {
        #pragma unroll
        for (int mt = 0; mt < 4; mt++) {
            const uint32_t ad = stageAddr + a_base + (uint32_t)((mt * 16 * BKP + kb) * 2);
            LDSM_X4(afr[buf][mt][0], afr[buf][mt][1], afr[buf][mt][2], afr[buf][mt][3], ad);
        }
        #pragma unroll
        for (int ntp = 0; ntp < 4; ntp++) {
            const uint32_t bd = stageAddr + b_base + (uint32_t)((ntp * 16 * BKP + kb) * 2);
            LDSM_X4(bfr[buf][2 * ntp][0], bfr[buf][2 * ntp][1],
                    bfr[buf][2 * ntp + 1][0], bfr[buf][2 * ntp + 1][1], bd);
        }
    };

    const int KT = K / BK;
    load_tile(0);
    load_tile(1);
    asm volatile("cp.async.wait_group 1;\n");
    __syncthreads();
    frag_load(0, smem0, 0);

    for (int kt = 0; kt < KT; kt++) {
        const uint32_t curA = smem0 + (uint32_t)((kt % NSTAGE) * STAGE_H * 2);
        const uint32_t nxtA = smem0 + (uint32_t)(((kt + 1) % NSTAGE) * STAGE_H * 2);
        if (kt + 2 < KT) load_tile(kt + 2);

        #pragma unroll
        for (int kk = 0; kk < 4; kk++) {
            const int buf = kk & 1;
            if (kk < 3) {
                frag_load(buf ^ 1, curA, (kk + 1) * 16);
            } else if (kt + 1 < KT) {
                if (kt + 2 < KT) { asm volatile("cp.async.wait_group 1;\n"); }
                else             { asm volatile("cp.async.wait_group 0;\n"); }
                __syncthreads();
                frag_load(buf ^ 1, nxtA, 0);
            }
            #pragma unroll
            for (int mt = 0; mt < 4; mt++)
                #pragma unroll
                for (int nt = 0; nt < 8; nt++) {
                    float* d = acc[mt][nt];
                    asm volatile(
                        "mma.sync.aligned.m16n8k16.row.col.f32.f16.f16.f32 "
                        "{%0,%1,%2,%3}, {%4,%5,%6,%7}, {%8,%9}, {%0,%1,%2,%3};\n"
                        : "+f"(d[0]), "+f"(d[1]), "+f"(d[2]), "+f"(d[3])
                        : "r"(afr[buf][mt][0]), "r"(afr[buf][mt][1]),
                          "r"(afr[buf][mt][2]), "r"(afr[buf][mt][3]),
                          "r"(bfr[buf][nt][0]), "r"(bfr[buf][nt][1]));
                }
        }
    }

    #pragma unroll
    for (int mt = 0; mt < 4; mt++) {
        const int row = bm + wm * 64 + mt * 16 + (lane >> 2);
        #pragma unroll
        for (int nt = 0; nt < 8; nt++) {
            const int col = bn + wn * 64 + nt * 8 + (lane & 3) * 2;
            float b0 = 0.f, b1 = 0.f;
            if (bias) { b0 = bias[col]; b1 = bias[col + 1]; }
            const float* d = acc[mt][nt];
            const float v0 = (d[0] + b0) * alpha;
            const float v1 = (d[1] + b1) * alpha;
            const float v2 = (d[2] + b0) * alpha;
            const float v3 = (d[3] + b1) * alpha;
            if constexpr (sizeof(OutT) == 2) {
                *reinterpret_cast<__half2*>((__half*)Cb + (size_t)(row    ) * ldc + col) =
                    __floats2half2_rn(v0, v1);
                *reinterpret_cast<__half2*>((__half*)Cb + (size_t)(row + 8) * ldc + col) =
                    __floats2half2_rn(v2, v3);
            } else {
                *reinterpret_cast<float2*>((float*)Cb + (size_t)(row    ) * ldc + col) =
                    make_float2(v0, v1);
                *reinterpret_cast<float2*>((float*)Cb + (size_t)(row + 8) * ldc + col) =
                    make_float2(v2, v3);
            }
        }
    }
}

// ---------------- fp32 -> fp16 (rna) bulk converts ----------------
__global__ void to_half2seg(const float* __restrict__ x0, __half* __restrict__ y0,
                            const float* __restrict__ x1, __half* __restrict__ y1,
                            long n)
{
    const float* x = blockIdx.y ? x1 : x0;
    __half*      y = blockIdx.y ? y1 : y0;
    long i = ((long)blockIdx.x * blockDim.x + threadIdx.x) * 8;
    if (i >= n) return;
    const float4 v0 = *reinterpret_cast<const float4*>(x + i);
    const float4 v1 = *reinterpret_cast<const float4*>(x + i + 4);
    __half2 h[4];
    h[0] = __floats2half2_rn(v0.x, v0.y);
    h[1] = __floats2half2_rn(v0.z, v0.w);
    h[2] = __floats2half2_rn(v1.x, v1.y);
    h[3] = __floats2half2_rn(v1.z, v1.w);
    *reinterpret_cast<uint4*>(y + i) = *reinterpret_cast<const uint4*>(h);
}

__global__ void to_half_w(const float* __restrict__ w0, const float* __restrict__ w1,
                          const float* __restrict__ w2, const float* __restrict__ w3,
                          const float* __restrict__ w4, __half* __restrict__ y,
                          long n)
{
    const float* x;
    switch (blockIdx.y) {
        case 0: x = w0; break;
        case 1: x = w1; break;
        case 2: x = w2; break;
        case 3: x = w3; break;
        default: x = w4; break;
    }
    __half* yp = y + (long)blockIdx.y * n;
    long i = ((long)blockIdx.x * blockDim.x + threadIdx.x) * 8;
    if (i >= n) return;
    const float4 v0 = *reinterpret_cast<const float4*>(x + i);
    const float4 v1 = *reinterpret_cast<const float4*>(x + i + 4);
    __half2 h[4];
    h[0] = __floats2half2_rn(v0.x, v0.y);
    h[1] = __floats2half2_rn(v0.z, v0.w);
    h[2] = __floats2half2_rn(v1.x, v1.y);
    h[3] = __floats2half2_rn(v1.z, v1.w);
    *reinterpret_cast<uint4*>(yp + i) = *reinterpret_cast<const uint4*>(h);
}

// ---------------- softmax over 512: fp32 out + fp16 copy ----------------
__global__ void softmax512(const float* __restrict__ S,
                           float* __restrict__ Ofull,
                           __half* __restrict__ Oh)
{
    const long row = blockIdx.x;
    const int tid = threadIdx.x;
    const float4 v = ((const float4*)(S + row * 512))[tid];

    float m = fmaxf(fmaxf(v.x, v.y), fmaxf(v.z, v.w));
    #pragma unroll
    for (int off = 16; off; off >>= 1) m = fmaxf(m, __shfl_xor_sync(~0u, m, off));
    __shared__ float redm[4];
    if ((tid & 31) == 0) redm[tid >> 5] = m;
    __syncthreads();
    m = fmaxf(fmaxf(redm[0], redm[1]), fmaxf(redm[2], redm[3]));

    const float e0 = __expf(v.x - m), e1 = __expf(v.y - m);
    const float e2 = __expf(v.z - m), e3 = __expf(v.w - m);
    float s = e0 + e1 + e2 + e3;
    #pragma unroll
    for (int off = 16; off; off >>= 1) s += __shfl_xor_sync(~0u, s, off);
    __shared__ float reds[4];
    if ((tid & 31) == 0) reds[tid >> 5] = s;
    __syncthreads();
    s = reds[0] + reds[1] + reds[2] + reds[3];

    const float inv = 1.0f / s;
    const float p0 = e0 * inv, p1 = e1 * inv, p2 = e2 * inv, p3 = e3 * inv;
    ((float4*)(Ofull + row * 512))[tid] = make_float4(p0, p1, p2, p3);
    __half2 h[2] = { __floats2half2_rn(p0, p1), __floats2half2_rn(p2, p3) };
    ((uint2*)(Oh + row * 512))[tid] = *reinterpret_cast<const uint2*>(h);
}

// ---------------- launcher ----------------
extern "C" void kernel_launch(void* const* d_in, const int* in_sizes, int n_in,
                              void* d_out, int out_size)
{
    const float* sent = (const float*)d_in[0];
    const float* pos  = (const float*)d_in[1];
    // d_in[2] = branch_emb: unused by the reference
    const float* Wq   = (const float*)d_in[3];
    const float* bq   = (const float*)d_in[4];
    const float* Wk   = (const float*)d_in[5];
    const float* bk   = (const float*)d_in[6];
    const float* Wv   = (const float*)d_in[7];
    const float* bv   = (const float*)d_in[8];
    const float* Wpq  = (const float*)d_in[9];
    const float* bpq  = (const float*)d_in[10];
    const float* Wpk  = (const float*)d_in[11];
    const float* bpk  = (const float*)d_in[12];
    const float* bias = (const float*)d_in[13];
    float* out = (float*)d_out;

    __half *Ah, *Ph, *Wh, *Qc, *Kc, *V, *At;
    float *Sc;
    cudaGetSymbolAddress((void**)&Ah, g_Ah);
    cudaGetSymbolAddress((void**)&Ph, g_Ph);
    cudaGetSymbolAddress((void**)&Wh, g_Wh);
    cudaGetSymbolAddress((void**)&Qc, g_Qc);
    cudaGetSymbolAddress((void**)&Kc, g_Kc);
    cudaGetSymbolAddress((void**)&V,  g_V);
    cudaGetSymbolAddress((void**)&At, g_At);
    cudaGetSymbolAddress((void**)&Sc, g_S);

    cudaFuncSetAttribute(gemm_nt_f16<__half>, cudaFuncAttributeMaxDynamicSharedMemorySize, SMEM_BYTES);
    cudaFuncSetAttribute(gemm_nt_f16<float>,  cudaFuncAttributeMaxDynamicSharedMemorySize, SMEM_BYTES);

    const long nEmb = (long)Bv * Sv * 512;
    const long nW   = 512L * 512;
    const float norm = 0.03125f;               // 1/sqrt(2*512), exact pow2
    const long  M     = (long)Bv * Sv;
    const long  rowQK = 512L * 1024;
    const long  rowSS = 512L * 512;

    // Stage 0: rna-convert operands to fp16
    {
        dim3 ge((unsigned)(nEmb / 4096), 2);
        to_half2seg<<<ge, 512>>>(sent, Ah, pos, Ph, nEmb);
        dim3 gw((unsigned)(nW / 4096), 5);
        to_half_w<<<gw, 512>>>(Wq, Wk, Wv, Wpq, Wpk, Wh, nW);
    }

    // Stage 1: projections (M=32768, N=512, K=512) -> fp16 intermediates
    dim3 g1((unsigned)(M / BM), 512 / BN, 1);
    gemm_nt_f16<__half><<<g1, THREADS, SMEM_BYTES>>>(Ah, 512, 0, Wh + 0 * nW, 512, 0, bq,  norm, Qc,       1024, 0, 512);
    gemm_nt_f16<__half><<<g1, THREADS, SMEM_BYTES>>>(Ph, 512, 0, Wh + 3 * nW, 512, 0, bpq, norm, Qc + 512, 1024, 0, 512);
    gemm_nt_f16<__half><<<g1, THREADS, SMEM_BYTES>>>(Ah, 512, 0, Wh + 1 * nW, 512, 0, bk,  1.f,  Kc,       1024, 0, 512);
    gemm_nt_f16<__half><<<g1, THREADS, SMEM_BYTES>>>(Ph, 512, 0, Wh + 4 * nW, 512, 0, bpk, 1.f,  Kc + 512, 1024, 0, 512);
    gemm_nt_f16<__half><<<g1, THREADS, SMEM_BYTES>>>(Ah, 512, 0, Wh + 2 * nW, 512, 0, bv,  1.f,  V,         512, 0, 512);

    // Stage 2: fused text+pos scores per batch (K=1024) + bias -> fp32
    dim3 g2(Sv / BM, Sv / BN, Bv);
    gemm_nt_f16<float><<<g2, THREADS, SMEM_BYTES>>>(Qc, 1024, rowQK, Kc, 1024, rowQK, bias, 1.f, Sc, 512, rowSS, 1024);

    // Stage 3: softmax -> d_out first half (fp32) + fp16 att
    softmax512<<<(unsigned)M, 128>>>(Sc, out, At);

    // Stage 4: output[b] = att_b @ V_b^T -> d_out second half
    gemm_nt_f16<float><<<g2, THREADS, SMEM_BYTES>>>(At, 512, rowSS, V, 512, rowSS, nullptr, 1.f,
                                                    out + (long)Bv * rowSS, 512, rowSS, 512);
}

// round 11
// speedup vs baseline: 1.2676x; 1.2676x over previous
#include <cuda_runtime.h>
#include <cuda_fp16.h>
#include <cstdint>

// ---------------------------------------------------------------------------
// Conversation_Self_Attention: B=64, S=512, D=DK=DV=512  (sm_103 mma.sync;
// tcgen05 unavailable in this bench path)
//
// fp16 HMMA (m16n8k16, fp32 accum), ldmatrix, 128x128 CTA, 128 thr / 4 warps
// (64x64 warp tiles), BK=64, 3-stage cp.async, ONE barrier per k-chunk,
// register fragment double-buffering, 2 CTAs/SM.  NEW vs R9:
//   - cp.async interleaved into the kk sub-steps (4 ops per kk) so the LSU
//     drains during HMMA issue instead of serializing at chunk start
//   - all 5 projection GEMMs in one z=5 launch (no inter-launch tails)
//
//   Qc = [ half((sent@Wq^T+bq)*2^-5) | half((pos@Wpq^T+bpq)*2^-5) ] [B*S,1024]
//   Kc = [ half(sent@Wk^T+bk)        | half(pos@Wpk^T+bpk)        ] [B*S,1024]
//   V  =   half(sent@Wv^T+bv)                                       [B*S,512]
//   scores[b] = Qc_b @ Kc_b^T + bias   (fp32)
//   att = softmax(scores) -> d_out[0:B*S*S] fp32 + half copy
//   out[b] = att_b @ V_b^T -> d_out[B*S*S:] fp32
// ---------------------------------------------------------------------------

#define BM 128
#define BN 128
#define BK 64                 // halves per k-chunk (128B)
#define BKP 72                // padded row (144B): conflict-free ldmatrix
#define NSTAGE 3
#define THREADS 128
#define TILE_H (BM * BKP)                      // 9216 halves per tile
#define STAGE_H (2 * TILE_H)
#define SMEM_BYTES (NSTAGE * STAGE_H * 2)      // 110592

static const int Bv = 64, Sv = 512;

// scratch (static device arrays: allocation-free contract)
__device__ __align__(128) __half g_Ah[64L * 512 * 512];
__device__ __align__(128) __half g_Ph[64L * 512 * 512];
__device__ __align__(128) __half g_Wh[5L * 512 * 512];
__device__ __align__(128) __half g_Qc[64L * 512 * 1024];
__device__ __align__(128) __half g_Kc[64L * 512 * 1024];
__device__ __align__(128) __half g_V [64L * 512 * 512];
__device__ __align__(128) __half g_At[64L * 512 * 512];
__device__ float g_S[64L * 512 * 512];

__device__ __forceinline__ uint32_t smem_u32(const void* p) {
    uint32_t a;
    asm("{ .reg .u64 t; cvta.to.shared.u64 t, %1; cvt.u32.u64 %0, t; }" : "=r"(a) : "l"(p));
    return a;
}

#define LDSM_X4(r0, r1, r2, r3, addr)                                  \
    asm volatile("ldmatrix.sync.aligned.m8n8.x4.shared.b16 "           \
                 "{%0, %1, %2, %3}, [%4];"                             \
                 : "=r"(r0), "=r"(r1), "=r"(r2), "=r"(r3) : "r"(addr))

// ---------------- shared GEMM body: C = (A @ B^T + bias) * alpha ------------
template <typename OutT>
__device__ __forceinline__ void gemm_body(
    const __half* __restrict__ Ab, int lda,
    const __half* __restrict__ Bb, int ldb,
    const float* __restrict__ bias, float alpha,
    OutT* __restrict__ Cb, int ldc, int K,
    __half* smem)
{
    const int tid  = threadIdx.x;
    const int lane = tid & 31;
    const int warp = tid >> 5;
    const int wm   = warp & 1;            // 2 warps in M -> 64 rows/warp
    const int wn   = warp >> 1;           // 2 warps in N -> 64 cols/warp

    const int bm = blockIdx.x * BM;
    const int bn = blockIdx.y * BN;

    // cp.async coords: 128B global rows = 8 x 16B chunks (128 thr -> 16 rows/pass)
    const int row8 = tid >> 3;            // 0..15
    const int ch   = tid & 7;

    // ldmatrix per-thread coords (mapping verified R5-R10)
    const int g  = lane >> 3;             // matrix index 0..3
    const int lr = lane & 7;
    const uint32_t a_base = (uint32_t)(((wm * 64 + (g & 1) * 8 + lr) * BKP) + (g >> 1) * 8) * 2;
    const uint32_t b_base = (uint32_t)(((wn * 64 + (g >> 1) * 8 + lr) * BKP) + (g & 1) * 8) * 2
                          + TILE_H * 2;

    const uint32_t smem0 = smem_u32(smem);

    float acc[4][8][4];
    #pragma unroll
    for (int i = 0; i < 4; i++)
        #pragma unroll
        for (int j = 0; j < 8; j++)
            #pragma unroll
            for (int k = 0; k < 4; k++) acc[i][j][k] = 0.f;

    unsigned afr[2][4][4], bfr[2][8][2];

    // 2 A-rows + 2 B-rows of one k-chunk (part 0..3 covers the full tile pair)
    auto load_part = [&](int kt, int part) {
        const int st = kt % NSTAGE;
        __half* dA = smem + st * STAGE_H;
        __half* dB = dA + TILE_H;
        const int k0 = kt * BK;
        #pragma unroll
        for (int i = part * 2; i < part * 2 + 2; i++) {
            const int row = row8 + i * 16;
            {
                const __half* gp = Ab + (size_t)(bm + row) * lda + k0 + ch * 8;
                unsigned s = (unsigned)__cvta_generic_to_shared(dA + row * BKP + ch * 8);
                asm volatile("cp.async.cg.shared.global [%0], [%1], 16;\n" :: "r"(s), "l"(gp));
            }
            {
                const __half* gp = Bb + (size_t)(bn + row) * ldb + k0 + ch * 8;
                unsigned s = (unsigned)__cvta_generic_to_shared(dB + row * BKP + ch * 8);
                asm volatile("cp.async.cg.shared.global [%0], [%1], 16;\n" :: "r"(s), "l"(gp));
            }
        }
    };

    auto frag_load = [&](int buf, uint32_t stageAddr, int kb) {
        #pragma unroll
        for (int mt = 0; mt < 4; mt++) {
            const uint32_t ad = stageAddr + a_base + (uint32_t)((mt * 16 * BKP + kb) * 2);
            LDSM_X4(afr[buf][mt][0], afr[buf][mt][1], afr[buf][mt][2], afr[buf][mt][3], ad);
        }
        #pragma unroll
        for (int ntp = 0; ntp < 4; ntp++) {
            const uint32_t bd = stageAddr + b_base + (uint32_t)((ntp * 16 * BKP + kb) * 2);
            LDSM_X4(bfr[buf][2 * ntp][0], bfr[buf][2 * ntp][1],
                    bfr[buf][2 * ntp + 1][0], bfr[buf][2 * ntp + 1][1], bd);
        }
    };

    const int KT = K / BK;
    // prologue: chunks 0 and 1 fully in flight
    #pragma unroll
    for (int p = 0; p < 4; p++) load_part(0, p);
    asm volatile("cp.async.commit_group;\n");
    #pragma unroll
    for (int p = 0; p < 4; p++) load_part(1, p);
    asm volatile("cp.async.commit_group;\n");
    asm volatile("cp.async.wait_group 1;\n");
    __syncthreads();
    frag_load(0, smem0, 0);

    for (int kt = 0; kt < KT; kt++) {
        const uint32_t curA = smem0 + (uint32_t)((kt % NSTAGE) * STAGE_H * 2);
        const uint32_t nxtA = smem0 + (uint32_t)(((kt + 1) % NSTAGE) * STAGE_H * 2);

        #pragma unroll
        for (int kk = 0; kk < 4; kk++) {
            const int buf = kk & 1;
            if (kk < 3) {
                frag_load(buf ^ 1, curA, (kk + 1) * 16);
                if (kt + 2 < KT) load_part(kt + 2, kk);     // 4 cp.async in HMMA shadow
            } else {
                if (kt + 2 < KT) {
                    load_part(kt + 2, 3);
                    asm volatile("cp.async.commit_group;\n");
                }
                if (kt + 1 < KT) {
                    if (kt + 2 < KT) { asm volatile("cp.async.wait_group 1;\n"); }
                    else             { asm volatile("cp.async.wait_group 0;\n"); }
                    __syncthreads();
                    frag_load(buf ^ 1, nxtA, 0);
                }
            }
            #pragma unroll
            for (int mt = 0; mt < 4; mt++)
                #pragma unroll
                for (int nt = 0; nt < 8; nt++) {
                    float* d = acc[mt][nt];
                    asm volatile(
                        "mma.sync.aligned.m16n8k16.row.col.f32.f16.f16.f32 "
                        "{%0,%1,%2,%3}, {%4,%5,%6,%7}, {%8,%9}, {%0,%1,%2,%3};\n"
                        : "+f"(d[0]), "+f"(d[1]), "+f"(d[2]), "+f"(d[3])
                        : "r"(afr[buf][mt][0]), "r"(afr[buf][mt][1]),
                          "r"(afr[buf][mt][2]), "r"(afr[buf][mt][3]),
                          "r"(bfr[buf][nt][0]), "r"(bfr[buf][nt][1]));
                }
        }
    }

    #pragma unroll
    for (int mt = 0; mt < 4; mt++) {
        const int row = bm + wm * 64 + mt * 16 + (lane >> 2);
        #pragma unroll
        for (int nt = 0; nt < 8; nt++) {
            const int col = bn + wn * 64 + nt * 8 + (lane & 3) * 2;
            float b0 = 0.f, b1 = 0.f;
            if (bias) { b0 = bias[col]; b1 = bias[col + 1]; }
            const float* d = acc[mt][nt];
            const float v0 = (d[0] + b0) * alpha;
            const float v1 = (d[1] + b1) * alpha;
            const float v2 = (d[2] + b0) * alpha;
            const float v3 = (d[3] + b1) * alpha;
            if constexpr (sizeof(OutT) == 2) {
                *reinterpret_cast<__half2*>((__half*)Cb + (size_t)(row    ) * ldc + col) =
                    __floats2half2_rn(v0, v1);
                *reinterpret_cast<__half2*>((__half*)Cb + (size_t)(row + 8) * ldc + col) =
                    __floats2half2_rn(v2, v3);
            } else {
                *reinterpret_cast<float2*>((float*)Cb + (size_t)(row    ) * ldc + col) =
                    make_float2(v0, v1);
                *reinterpret_cast<float2*>((float*)Cb + (size_t)(row + 8) * ldc + col) =
                    make_float2(v2, v3);
            }
        }
    }
}

// ---------------- all-5-projections kernel (z selects operand set) ----------
struct Proj5 {
    const __half* A[5];
    const float*  bias[5];
    __half*       C[5];
    int           ldc[5];
    float         alpha[5];
};

__global__ void __launch_bounds__(THREADS, 2)
gemm_proj(Proj5 p, const __half* __restrict__ W, long wstride, int K)
{
    extern __shared__ __half smem[];
    const int z = blockIdx.z;
    gemm_body<__half>(p.A[z], 512, W + (size_t)z * wstride, 512,
                      p.bias[z], p.alpha[z], p.C[z], p.ldc[z], K, smem);
}

// ---------------- batched GEMM kernel (z = batch index) ----------
template <typename OutT>
__global__ void __launch_bounds__(THREADS, 2)
gemm_batch(const __half* __restrict__ A, int lda, long As,
           const __half* __restrict__ B, int ldb, long Bs,
           const float* __restrict__ bias, float alpha,
           OutT* __restrict__ C, int ldc, long Cs,
           int K)
{
    extern __shared__ __half smem[];
    const int z = blockIdx.z;
    gemm_body<OutT>(A + (size_t)z * As, lda, B + (size_t)z * Bs, ldb,
                    bias, alpha, C + (size_t)z * Cs, ldc, K, smem);
}

// ---------------- fp32 -> fp16 (rna) bulk converts ----------------
__global__ void to_half2seg(const float* __restrict__ x0, __half* __restrict__ y0,
                            const float* __restrict__ x1, __half* __restrict__ y1,
                            long n)
{
    const float* x = blockIdx.y ? x1 : x0;
    __half*      y = blockIdx.y ? y1 : y0;
    long i = ((long)blockIdx.x * blockDim.x + threadIdx.x) * 8;
    if (i >= n) return;
    const float4 v0 = *reinterpret_cast<const float4*>(x + i);
    const float4 v1 = *reinterpret_cast<const float4*>(x + i + 4);
    __half2 h[4];
    h[0] = __floats2half2_rn(v0.x, v0.y);
    h[1] = __floats2half2_rn(v0.z, v0.w);
    h[2] = __floats2half2_rn(v1.x, v1.y);
    h[3] = __floats2half2_rn(v1.z, v1.w);
    *reinterpret_cast<uint4*>(y + i) = *reinterpret_cast<const uint4*>(h);
}

__global__ void to_half_w(const float* __restrict__ w0, const float* __restrict__ w1,
                          const float* __restrict__ w2, const float* __restrict__ w3,
                          const float* __restrict__ w4, __half* __restrict__ y,
                          long n)
{
    const float* x;
    switch (blockIdx.y) {
        case 0: x = w0; break;
        case 1: x = w1; break;
        case 2: x = w2; break;
        case 3: x = w3; break;
        default: x = w4; break;
    }
    __half* yp = y + (long)blockIdx.y * n;
    long i = ((long)blockIdx.x * blockDim.x + threadIdx.x) * 8;
    if (i >= n) return;
    const float4 v0 = *reinterpret_cast<const float4*>(x + i);
    const float4 v1 = *reinterpret_cast<const float4*>(x + i + 4);
    __half2 h[4];
    h[0] = __floats2half2_rn(v0.x, v0.y);
    h[1] = __floats2half2_rn(v0.z, v0.w);
    h[2] = __floats2half2_rn(v1.x, v1.y);
    h[3] = __floats2half2_rn(v1.z, v1.w);
    *reinterpret_cast<uint4*>(yp + i) = *reinterpret_cast<const uint4*>(h);
}

// ---------------- softmax over 512: fp32 out + fp16 copy ----------------
__global__ void softmax512(const float* __restrict__ S,
                           float* __restrict__ Ofull,
                           __half* __restrict__ Oh)
{
    const long row = blockIdx.x;
    const int tid = threadIdx.x;
    const float4 v = ((const float4*)(S + row * 512))[tid];

    float m = fmaxf(fmaxf(v.x, v.y), fmaxf(v.z, v.w));
    #pragma unroll
    for (int off = 16; off; off >>= 1) m = fmaxf(m, __shfl_xor_sync(~0u, m, off));
    __shared__ float redm[4];
    if ((tid & 31) == 0) redm[tid >> 5] = m;
    __syncthreads();
    m = fmaxf(fmaxf(redm[0], redm[1]), fmaxf(redm[2], redm[3]));

    const float e0 = __expf(v.x - m), e1 = __expf(v.y - m);
    const float e2 = __expf(v.z - m), e3 = __expf(v.w - m);
    float s = e0 + e1 + e2 + e3;
    #pragma unroll
    for (int off = 16; off; off >>= 1) s += __shfl_xor_sync(~0u, s, off);
    __shared__ float reds[4];
    if ((tid & 31) == 0) reds[tid >> 5] = s;
    __syncthreads();
    s = reds[0] + reds[1] + reds[2] + reds[3];

    const float inv = 1.0f / s;
    const float p0 = e0 * inv, p1 = e1 * inv, p2 = e2 * inv, p3 = e3 * inv;
    ((float4*)(Ofull + row * 512))[tid] = make_float4(p0, p1, p2, p3);
    __half2 h[2] = { __floats2half2_rn(p0, p1), __floats2half2_rn(p2, p3) };
    ((uint2*)(Oh + row * 512))[tid] = *reinterpret_cast<const uint2*>(h);
}

// ---------------- launcher ----------------
extern "C" void kernel_launch(void* const* d_in, const int* in_sizes, int n_in,
                              void* d_out, int out_size)
{
    const float* sent = (const float*)d_in[0];
    const float* pos  = (const float*)d_in[1];
    // d_in[2] = branch_emb: unused by the reference
    const float* Wq   = (const float*)d_in[3];
    const float* bq   = (const float*)d_in[4];
    const float* Wk   = (const float*)d_in[5];
    const float* bk   = (const float*)d_in[6];
    const float* Wv   = (const float*)d_in[7];
    const float* bv   = (const float*)d_in[8];
    const float* Wpq  = (const float*)d_in[9];
    const float* bpq  = (const float*)d_in[10];
    const float* Wpk  = (const float*)d_in[11];
    const float* bpk  = (const float*)d_in[12];
    const float* bias = (const float*)d_in[13];
    float* out = (float*)d_out;

    __half *Ah, *Ph, *Wh, *Qc, *Kc, *V, *At;
    float *Sc;
    cudaGetSymbolAddress((void**)&Ah, g_Ah);
    cudaGetSymbolAddress((void**)&Ph, g_Ph);
    cudaGetSymbolAddress((void**)&Wh, g_Wh);
    cudaGetSymbolAddress((void**)&Qc, g_Qc);
    cudaGetSymbolAddress((void**)&Kc, g_Kc);
    cudaGetSymbolAddress((void**)&V,  g_V);
    cudaGetSymbolAddress((void**)&At, g_At);
    cudaGetSymbolAddress((void**)&Sc, g_S);

    cudaFuncSetAttribute(gemm_proj,          cudaFuncAttributeMaxDynamicSharedMemorySize, SMEM_BYTES);
    cudaFuncSetAttribute(gemm_batch<float>,  cudaFuncAttributeMaxDynamicSharedMemorySize, SMEM_BYTES);

    const long nEmb = (long)Bv * Sv * 512;
    const long nW   = 512L * 512;
    const float norm = 0.03125f;               // 1/sqrt(2*512), exact pow2
    const long  M     = (long)Bv * Sv;
    const long  rowQK = 512L * 1024;
    const long  rowSS = 512L * 512;

    // Stage 0: rna-convert operands to fp16
    {
        dim3 ge((unsigned)(nEmb / 4096), 2);
        to_half2seg<<<ge, 512>>>(sent, Ah, pos, Ph, nEmb);
        dim3 gw((unsigned)(nW / 4096), 5);
        // g_Wh order: Wq, Wpq, Wk, Wpk, Wv  (matches Proj5 z order below)
        to_half_w<<<gw, 512>>>(Wq, Wpq, Wk, Wpk, Wv, Wh, nW);
    }

    // Stage 1: all 5 projections, one launch (z selects operand set)
    {
        Proj5 p;
        p.A[0] = Ah;  p.bias[0] = bq;  p.C[0] = Qc;        p.ldc[0] = 1024; p.alpha[0] = norm;
        p.A[1] = Ph;  p.bias[1] = bpq; p.C[1] = Qc + 512;  p.ldc[1] = 1024; p.alpha[1] = norm;
        p.A[2] = Ah;  p.bias[2] = bk;  p.C[2] = Kc;        p.ldc[2] = 1024; p.alpha[2] = 1.f;
        p.A[3] = Ph;  p.bias[3] = bpk; p.C[3] = Kc + 512;  p.ldc[3] = 1024; p.alpha[3] = 1.f;
        p.A[4] = Ah;  p.bias[4] = bv;  p.C[4] = V;         p.ldc[4] = 512;  p.alpha[4] = 1.f;
        dim3 g1((unsigned)(M / BM), 512 / BN, 5);
        gemm_proj<<<g1, THREADS, SMEM_BYTES>>>(p, Wh, nW, 512);
    }

    // Stage 2: fused text+pos scores per batch (K=1024) + bias -> fp32
    dim3 g2(Sv / BM, Sv / BN, Bv);
    gemm_batch<float><<<g2, THREADS, SMEM_BYTES>>>(Qc, 1024, rowQK, Kc, 1024, rowQK,
                                                   bias, 1.f, Sc, 512, rowSS, 1024);

    // Stage 3: softmax -> d_out first half (fp32) + fp16 att
    softmax512<<<(unsigned)M, 128>>>(Sc, out, At);

    // Stage 4: output[b] = att_b @ V_b^T -> d_out second half
    gemm_batch<float><<<g2, THREADS, SMEM_BYTES>>>(At, 512, rowSS, V, 512, rowSS, nullptr, 1.f,
                                                   out + (long)Bv * rowSS, 512, rowSS, 512);
}